// round 1
// baseline (speedup 1.0000x reference)
#include <cuda_runtime.h>
#include <math.h>

// Problem constants
#define BB 2
#define TT 2048
#define EE 1024
#define HH 16
#define HD 64
#define DFF 4096
#define NTOK (BB*TT)          // 4096
#define BHN (BB*HH)           // 32

// ---------------- scratch (device globals; no allocation allowed) ----------------
__device__ float g_h   [NTOK*EE];          // LN1 output
__device__ float g_wqkv[EE*3*EE];          // packed [E, 3E] weights
__device__ float g_qkv [NTOK*3*EE];        // q|k|v per token
__device__ float g_att [(size_t)BHN*TT*TT];// scores -> probs (536 MB)
__device__ float g_o   [NTOK*EE];          // attention out (heads concat)
__device__ float g_x2  [NTOK*EE];          // h + proj
__device__ float g_h2  [NTOK*EE];          // LN2 output
__device__ float g_ffn [NTOK*DFF];         // relu(h2@w1+b1)

// ---------------- LayerNorm: one block per row of 1024 ----------------
__global__ void ln_kernel(const float* __restrict__ x,
                          const float* __restrict__ gamma,
                          const float* __restrict__ beta,
                          float* __restrict__ y)
{
    int row = blockIdx.x;
    const float* xr = x + (size_t)row * EE;
    float* yr = y + (size_t)row * EE;
    int tid = threadIdx.x;
    __shared__ float red[256];

    float s = 0.f;
    for (int i = tid; i < EE; i += 256) s += xr[i];
    red[tid] = s; __syncthreads();
    for (int o = 128; o > 0; o >>= 1) { if (tid < o) red[tid] += red[tid + o]; __syncthreads(); }
    float mean = red[0] * (1.0f / EE);
    __syncthreads();

    float v = 0.f;
    for (int i = tid; i < EE; i += 256) { float d = xr[i] - mean; v += d * d; }
    red[tid] = v; __syncthreads();
    for (int o = 128; o > 0; o >>= 1) { if (tid < o) red[tid] += red[tid + o]; __syncthreads(); }
    float inv = rsqrtf(red[0] * (1.0f / EE) + 1e-5f);

    for (int i = tid; i < EE; i += 256)
        yr[i] = (xr[i] - mean) * inv * gamma[i] + beta[i];
}

// ---------------- pack wq/wk/wv [H,E,hd] -> [E, 3E] ----------------
__global__ void pack_w_kernel(const float* __restrict__ wq,
                              const float* __restrict__ wk,
                              const float* __restrict__ wv,
                              float* __restrict__ out)
{
    int idx = blockIdx.x * blockDim.x + threadIdx.x;
    const int total = 3 * EE * EE;
    if (idx >= total) return;
    int part = idx / (EE * EE);
    int rem  = idx % (EE * EE);
    int e = rem / EE;
    int c = rem % EE;                 // c = h*64 + k
    const float* w = (part == 0) ? wq : (part == 1) ? wk : wv;
    out[(size_t)e * (3 * EE) + part * EE + c] =
        w[(size_t)(c >> 6) * (EE * HD) + (size_t)e * HD + (c & 63)];
}

// ---------------- generic SGEMM: C[M,N] = A[M,K] @ B[K,N] (+epilogue) --------
// EPI: 0 = none; 1 = +bias; 2 = relu(+bias); 3 = +bias +res
template <int EPI>
__global__ void sgemm_kernel(const float* __restrict__ A,
                             const float* __restrict__ B,
                             const float* __restrict__ bias,
                             const float* __restrict__ res,
                             float* __restrict__ C,
                             int M, int N, int K)
{
    const int BM = 64, BN = 64, BK = 16;
    __shared__ float As[BK][BM + 4];
    __shared__ float Bs[BK][BN + 4];
    int tid = threadIdx.x;            // 256 threads
    int ty = tid >> 4, tx = tid & 15;
    int rowBase = blockIdx.y * BM;
    int colBase = blockIdx.x * BN;
    float acc[4][4] = {};

    for (int k0 = 0; k0 < K; k0 += BK) {
        #pragma unroll
        for (int i = 0; i < 4; i++) {
            int lin = i * 256 + tid;
            int am = lin >> 4, ak = lin & 15;
            As[ak][am] = A[(size_t)(rowBase + am) * K + k0 + ak];
            int bk = lin >> 6, bn = lin & 63;
            Bs[bk][bn] = B[(size_t)(k0 + bk) * N + colBase + bn];
        }
        __syncthreads();
        #pragma unroll
        for (int kk = 0; kk < BK; kk++) {
            float a[4], b[4];
            #pragma unroll
            for (int i = 0; i < 4; i++) a[i] = As[kk][ty * 4 + i];
            #pragma unroll
            for (int j = 0; j < 4; j++) b[j] = Bs[kk][tx * 4 + j];
            #pragma unroll
            for (int i = 0; i < 4; i++)
                #pragma unroll
                for (int j = 0; j < 4; j++)
                    acc[i][j] += a[i] * b[j];
        }
        __syncthreads();
    }

    #pragma unroll
    for (int i = 0; i < 4; i++) {
        int row = rowBase + ty * 4 + i;
        #pragma unroll
        for (int j = 0; j < 4; j++) {
            int col = colBase + tx * 4 + j;
            float v = acc[i][j];
            if (EPI >= 1) v += bias[col];
            if (EPI == 2) v = fmaxf(v, 0.0f);
            if (EPI == 3) v += res[(size_t)row * N + col];
            C[(size_t)row * N + col] = v;
        }
    }
}

// ---------------- QK^T with causal tile skipping ----------------
// grid: (T/64, T/64, BH); block: 256
__global__ void qk_kernel(const float* __restrict__ qkv, float* __restrict__ att)
{
    int bh = blockIdx.z;
    int b = bh >> 4, h = bh & 15;
    int rt = blockIdx.y, ct = blockIdx.x;
    if (ct > rt) return;   // strictly upper tiles never read

    __shared__ float Qs[64][65], Ks[64][65];
    int tid = threadIdx.x;
    const size_t qbase = ((size_t)(b * TT) + rt * 64) * (3 * EE) + (size_t)h * HD;
    const size_t kbase = ((size_t)(b * TT) + ct * 64) * (3 * EE) + EE + (size_t)h * HD;
    #pragma unroll
    for (int i = 0; i < 16; i++) {
        int lin = i * 256 + tid;
        int r = lin >> 6, c = lin & 63;
        Qs[r][c] = qkv[qbase + (size_t)r * (3 * EE) + c];
        Ks[r][c] = qkv[kbase + (size_t)r * (3 * EE) + c];
    }
    __syncthreads();

    int ty = tid >> 4, tx = tid & 15;
    float acc[4][4] = {};
    #pragma unroll 8
    for (int k = 0; k < 64; k++) {
        float a[4], bv[4];
        #pragma unroll
        for (int i = 0; i < 4; i++) a[i]  = Qs[ty * 4 + i][k];
        #pragma unroll
        for (int j = 0; j < 4; j++) bv[j] = Ks[tx * 4 + j][k];
        #pragma unroll
        for (int i = 0; i < 4; i++)
            #pragma unroll
            for (int j = 0; j < 4; j++)
                acc[i][j] += a[i] * bv[j];
    }

    const float scale = 0.125f; // 1/sqrt(64)
    size_t abase = (size_t)bh * TT * TT;
    #pragma unroll
    for (int i = 0; i < 4; i++) {
        int t = rt * 64 + ty * 4 + i;
        #pragma unroll
        for (int j = 0; j < 4; j++) {
            int s = ct * 64 + tx * 4 + j;
            if (s <= t) att[abase + (size_t)t * TT + s] = acc[i][j] * scale;
        }
    }
}

// ---------------- causal softmax per row (writes 0 above diagonal) ----------
__global__ void softmax_kernel(float* __restrict__ att)
{
    int r = blockIdx.x;               // BH*T rows
    int t = r & (TT - 1);
    float* row = att + (size_t)r * TT;
    int len = t + 1;
    int tid = threadIdx.x;
    __shared__ float red[256];

    float m = -INFINITY;
    for (int s = tid; s < len; s += 256) m = fmaxf(m, row[s]);
    red[tid] = m; __syncthreads();
    for (int o = 128; o > 0; o >>= 1) { if (tid < o) red[tid] = fmaxf(red[tid], red[tid + o]); __syncthreads(); }
    m = red[0];
    __syncthreads();

    float sum = 0.f;
    for (int s = tid; s < len; s += 256) { float e = __expf(row[s] - m); row[s] = e; sum += e; }
    red[tid] = sum; __syncthreads();
    for (int o = 128; o > 0; o >>= 1) { if (tid < o) red[tid] += red[tid + o]; __syncthreads(); }
    float inv = 1.0f / red[0];

    for (int s = tid; s < len; s += 256) row[s] *= inv;
    for (int s = len + tid; s < TT; s += 256) row[s] = 0.0f;
}

// ---------------- P @ V with causal s-tile bound ----------------
// grid: (1, T/64, BH); block 256; output tile [64 t][64 hd]
__global__ void pv_kernel(const float* __restrict__ att,
                          const float* __restrict__ qkv,
                          float* __restrict__ o)
{
    int bh = blockIdx.z;
    int b = bh >> 4, h = bh & 15;
    int rt = blockIdx.y;

    __shared__ float Ps[64][65], Vs[64][65];
    int tid = threadIdx.x;
    int ty = tid >> 4, tx = tid & 15;
    float acc[4][4] = {};

    size_t abase = (size_t)bh * TT * TT + (size_t)rt * 64 * TT;
    size_t vbase = (size_t)b * TT * (3 * EE) + 2 * EE + (size_t)h * HD;

    for (int st = 0; st <= rt; st++) {
        #pragma unroll
        for (int i = 0; i < 16; i++) {
            int lin = i * 256 + tid;
            int rr = lin >> 6, cc = lin & 63;
            Ps[rr][cc] = att[abase + (size_t)rr * TT + st * 64 + cc];
            Vs[rr][cc] = qkv[vbase + (size_t)(st * 64 + rr) * (3 * EE) + cc];
        }
        __syncthreads();
        #pragma unroll 8
        for (int k = 0; k < 64; k++) {
            float a[4], bv[4];
            #pragma unroll
            for (int i = 0; i < 4; i++) a[i]  = Ps[ty * 4 + i][k];
            #pragma unroll
            for (int j = 0; j < 4; j++) bv[j] = Vs[k][tx * 4 + j];
            #pragma unroll
            for (int i = 0; i < 4; i++)
                #pragma unroll
                for (int j = 0; j < 4; j++)
                    acc[i][j] += a[i] * bv[j];
        }
        __syncthreads();
    }

    size_t obase = ((size_t)(b * TT) + rt * 64) * EE + (size_t)h * HD;
    #pragma unroll
    for (int i = 0; i < 4; i++)
        #pragma unroll
        for (int j = 0; j < 4; j++)
            o[obase + (size_t)(ty * 4 + i) * EE + tx * 4 + j] = acc[i][j];
}

// ---------------- launcher ----------------
extern "C" void kernel_launch(void* const* d_in, const int* in_sizes, int n_in,
                              void* d_out, int out_size)
{
    const float* x      = (const float*)d_in[0];
    const float* wq     = (const float*)d_in[1];
    const float* wk     = (const float*)d_in[2];
    const float* wv     = (const float*)d_in[3];
    const float* w_proj = (const float*)d_in[4];
    const float* b_proj = (const float*)d_in[5];
    const float* gamma1 = (const float*)d_in[6];
    const float* beta1  = (const float*)d_in[7];
    const float* gamma2 = (const float*)d_in[8];
    const float* beta2  = (const float*)d_in[9];
    const float* w1     = (const float*)d_in[10];
    const float* b1     = (const float*)d_in[11];
    const float* w2     = (const float*)d_in[12];
    const float* b2     = (const float*)d_in[13];
    float* out = (float*)d_out;

    float *p_h, *p_wqkv, *p_qkv, *p_att, *p_o, *p_x2, *p_h2, *p_ffn;
    cudaGetSymbolAddress((void**)&p_h,    g_h);
    cudaGetSymbolAddress((void**)&p_wqkv, g_wqkv);
    cudaGetSymbolAddress((void**)&p_qkv,  g_qkv);
    cudaGetSymbolAddress((void**)&p_att,  g_att);
    cudaGetSymbolAddress((void**)&p_o,    g_o);
    cudaGetSymbolAddress((void**)&p_x2,   g_x2);
    cudaGetSymbolAddress((void**)&p_h2,   g_h2);
    cudaGetSymbolAddress((void**)&p_ffn,  g_ffn);

    // 1) LN1
    ln_kernel<<<NTOK, 256>>>(x, gamma1, beta1, p_h);
    // 2) pack per-head weights into [E,3E]
    pack_w_kernel<<<(3 * EE * EE) / 256, 256>>>(wq, wk, wv, p_wqkv);
    // 3) QKV = h @ Wqkv  [4096 x 3072]
    sgemm_kernel<0><<<dim3(3 * EE / 64, NTOK / 64), 256>>>(p_h, p_wqkv, nullptr, nullptr, p_qkv, NTOK, 3 * EE, EE);
    // 4) scores (causal tiles only)
    qk_kernel<<<dim3(TT / 64, TT / 64, BHN), 256>>>(p_qkv, p_att);
    // 5) softmax per row
    softmax_kernel<<<BHN * TT, 256>>>(p_att);
    // 6) O = P @ V (causal-bounded)
    pv_kernel<<<dim3(1, TT / 64, BHN), 256>>>(p_att, p_qkv, p_o);
    // 7) x2 = h + O @ w_proj + b_proj
    sgemm_kernel<3><<<dim3(EE / 64, NTOK / 64), 256>>>(p_o, w_proj, b_proj, p_h, p_x2, NTOK, EE, EE);
    // 8) LN2
    ln_kernel<<<NTOK, 256>>>(p_x2, gamma2, beta2, p_h2);
    // 9) ffn = relu(h2 @ w1 + b1)
    sgemm_kernel<2><<<dim3(DFF / 64, NTOK / 64), 256>>>(p_h2, w1, b1, nullptr, p_ffn, NTOK, DFF, EE);
    // 10) out = h2 + ffn @ w2 + b2
    sgemm_kernel<3><<<dim3(EE / 64, NTOK / 64), 256>>>(p_ffn, w2, b2, p_h2, out, NTOK, EE, DFF);
}

// round 2
// speedup vs baseline: 2.1950x; 2.1950x over previous
#include <cuda_runtime.h>
#include <math.h>
#include <stdint.h>

// Problem constants
#define BB 2
#define TT 2048
#define EE 1024
#define HH 16
#define HD 64
#define DFF 4096
#define NTOK (BB*TT)          // 4096
#define BHN (BB*HH)           // 32

// ---------------- scratch (device globals; no allocation allowed) ----------------
__device__ float g_h   [NTOK*EE];          // LN1 output
__device__ float g_wqkv[EE*3*EE];          // packed [E, 3E] weights
__device__ float g_qkv [NTOK*3*EE];        // q|k|v per token
__device__ float g_att [(size_t)BHN*TT*TT];// scores -> probs
__device__ float g_o   [NTOK*EE];          // attention out (heads concat)
__device__ float g_x2  [NTOK*EE];          // h + proj
__device__ float g_h2  [NTOK*EE];          // LN2 output
__device__ float g_ffn [NTOK*DFF];         // relu(h2@w1+b1)

// ---------------- helpers ----------------
__device__ __forceinline__ uint32_t cvt_tf32(float x) {
    uint32_t r;
    asm("cvt.rna.tf32.f32 %0, %1;" : "=r"(r) : "f"(x));
    return r;
}
__device__ __forceinline__ void cp16(void* s, const void* g) {
    uint32_t sa = (uint32_t)__cvta_generic_to_shared(s);
    asm volatile("cp.async.cg.shared.global [%0], [%1], 16;" :: "r"(sa), "l"(g));
}
__device__ __forceinline__ void cp_commit() { asm volatile("cp.async.commit_group;"); }
template<int N> __device__ __forceinline__ void cp_wait() {
    asm volatile("cp.async.wait_group %0;" :: "n"(N));
}

// ---------------- LayerNorm: one block per row of 1024 ----------------
__global__ void ln_kernel(const float* __restrict__ x,
                          const float* __restrict__ gamma,
                          const float* __restrict__ beta,
                          float* __restrict__ y)
{
    int row = blockIdx.x;
    const float* xr = x + (size_t)row * EE;
    float* yr = y + (size_t)row * EE;
    int tid = threadIdx.x;
    __shared__ float red[256];

    float s = 0.f;
    for (int i = tid; i < EE; i += 256) s += xr[i];
    red[tid] = s; __syncthreads();
    for (int o = 128; o > 0; o >>= 1) { if (tid < o) red[tid] += red[tid + o]; __syncthreads(); }
    float mean = red[0] * (1.0f / EE);
    __syncthreads();

    float v = 0.f;
    for (int i = tid; i < EE; i += 256) { float d = xr[i] - mean; v += d * d; }
    red[tid] = v; __syncthreads();
    for (int o = 128; o > 0; o >>= 1) { if (tid < o) red[tid] += red[tid + o]; __syncthreads(); }
    float inv = rsqrtf(red[0] * (1.0f / EE) + 1e-5f);

    for (int i = tid; i < EE; i += 256)
        yr[i] = (xr[i] - mean) * inv * gamma[i] + beta[i];
}

// ---------------- pack wq/wk/wv [H,E,hd] -> [E, 3E] ----------------
__global__ void pack_w_kernel(const float* __restrict__ wq,
                              const float* __restrict__ wk,
                              const float* __restrict__ wv,
                              float* __restrict__ out)
{
    int idx = blockIdx.x * blockDim.x + threadIdx.x;
    const int total = 3 * EE * EE;
    if (idx >= total) return;
    int part = idx / (EE * EE);
    int rem  = idx % (EE * EE);
    int e = rem / EE;
    int c = rem % EE;
    const float* w = (part == 0) ? wq : (part == 1) ? wk : wv;
    out[(size_t)e * (3 * EE) + part * EE + c] =
        w[(size_t)(c >> 6) * (EE * HD) + (size_t)e * HD + (c & 63)];
}

// ---------------- tf32 tensor-core GEMM: C[M,N] = A[M,K] @ B[K,N] -----------
// Block 128x128x16, 8 warps (4x2), warp tile 32x64 via m16n8k8 HMMA.
// EPI: 0 = none; 2 = relu(+bias); 3 = +bias +res
template <int EPI>
__global__ void __launch_bounds__(256, 2)
mm_tf32(const float* __restrict__ A,
        const float* __restrict__ B,
        const float* __restrict__ bias,
        const float* __restrict__ res,
        float* __restrict__ C,
        int M, int N, int K)
{
    const int BM = 128, BN = 128, BK = 16;
    __shared__ float As[2][BM][BK + 4];   // stride 20: banks (20g+c) distinct
    __shared__ float Bs[2][BK][BN + 8];   // stride 136: banks (8c+g) distinct

    int tid = threadIdx.x;
    int lane = tid & 31, wid = tid >> 5;
    int wm = wid >> 1, wn = wid & 1;      // 4 x 2 warp grid
    int g = lane >> 2, c = lane & 3;
    int rowBase = blockIdx.y * BM;
    int colBase = blockIdx.x * BN;

    float acc[2][8][4];
    #pragma unroll
    for (int i = 0; i < 2; i++)
        #pragma unroll
        for (int j = 0; j < 8; j++)
            #pragma unroll
            for (int k = 0; k < 4; k++) acc[i][j][k] = 0.f;

    // stage loader: 512 16B chunks for A, 512 for B
    auto load_stage = [&](int buf, int kk) {
        #pragma unroll
        for (int i = 0; i < 2; i++) {
            int idx = i * 256 + tid;
            int m = idx >> 2, ch = idx & 3;
            cp16(&As[buf][m][ch * 4], A + (size_t)(rowBase + m) * K + kk + ch * 4);
        }
        #pragma unroll
        for (int i = 0; i < 2; i++) {
            int idx = i * 256 + tid;
            int r = idx >> 5, ch = idx & 31;
            cp16(&Bs[buf][r][ch * 4], B + (size_t)(kk + r) * N + colBase + ch * 4);
        }
        cp_commit();
    };

    load_stage(0, 0);
    int nk = K / BK;
    for (int k0 = 0; k0 < nk; k0++) {
        int cur = k0 & 1;
        if (k0 + 1 < nk) { load_stage(cur ^ 1, (k0 + 1) * BK); cp_wait<1>(); }
        else            { cp_wait<0>(); }
        __syncthreads();

        #pragma unroll
        for (int ks = 0; ks < 2; ks++) {
            int kb = ks * 8;
            uint32_t af[2][4];
            #pragma unroll
            for (int mt = 0; mt < 2; mt++) {
                int m0 = wm * 32 + mt * 16;
                af[mt][0] = cvt_tf32(As[cur][m0 + g    ][kb + c    ]);
                af[mt][1] = cvt_tf32(As[cur][m0 + g + 8][kb + c    ]);
                af[mt][2] = cvt_tf32(As[cur][m0 + g    ][kb + c + 4]);
                af[mt][3] = cvt_tf32(As[cur][m0 + g + 8][kb + c + 4]);
            }
            uint32_t bf[8][2];
            #pragma unroll
            for (int nt = 0; nt < 8; nt++) {
                int n0 = wn * 64 + nt * 8;
                bf[nt][0] = cvt_tf32(Bs[cur][kb + c    ][n0 + g]);
                bf[nt][1] = cvt_tf32(Bs[cur][kb + c + 4][n0 + g]);
            }
            #pragma unroll
            for (int mt = 0; mt < 2; mt++)
                #pragma unroll
                for (int nt = 0; nt < 8; nt++)
                    asm volatile(
                        "mma.sync.aligned.m16n8k8.row.col.f32.tf32.tf32.f32 "
                        "{%0,%1,%2,%3},{%4,%5,%6,%7},{%8,%9},{%0,%1,%2,%3};"
                        : "+f"(acc[mt][nt][0]), "+f"(acc[mt][nt][1]),
                          "+f"(acc[mt][nt][2]), "+f"(acc[mt][nt][3])
                        : "r"(af[mt][0]), "r"(af[mt][1]), "r"(af[mt][2]), "r"(af[mt][3]),
                          "r"(bf[nt][0]), "r"(bf[nt][1]));
        }
        __syncthreads();
    }

    // epilogue: c0,c1 at (row0, col..col+1); c2,c3 at (row0+8, col..col+1)
    #pragma unroll
    for (int mt = 0; mt < 2; mt++) {
        int row0 = rowBase + wm * 32 + mt * 16 + g;
        #pragma unroll
        for (int nt = 0; nt < 8; nt++) {
            int col = colBase + wn * 64 + nt * 8 + c * 2;
            float v0 = acc[mt][nt][0], v1 = acc[mt][nt][1];
            float v2 = acc[mt][nt][2], v3 = acc[mt][nt][3];
            if (EPI >= 1) {
                float b0 = bias[col], b1 = bias[col + 1];
                v0 += b0; v1 += b1; v2 += b0; v3 += b1;
            }
            if (EPI == 2) {
                v0 = fmaxf(v0, 0.f); v1 = fmaxf(v1, 0.f);
                v2 = fmaxf(v2, 0.f); v3 = fmaxf(v3, 0.f);
            }
            if (EPI == 3) {
                v0 += res[(size_t)row0 * N + col];
                v1 += res[(size_t)row0 * N + col + 1];
                v2 += res[(size_t)(row0 + 8) * N + col];
                v3 += res[(size_t)(row0 + 8) * N + col + 1];
            }
            *reinterpret_cast<float2*>(&C[(size_t)row0 * N + col])       = make_float2(v0, v1);
            *reinterpret_cast<float2*>(&C[(size_t)(row0 + 8) * N + col]) = make_float2(v2, v3);
        }
    }
}

// ---------------- QK^T with causal tile skipping ----------------
__global__ void qk_kernel(const float* __restrict__ qkv, float* __restrict__ att)
{
    int bh = blockIdx.z;
    int b = bh >> 4, h = bh & 15;
    int rt = blockIdx.y, ct = blockIdx.x;
    if (ct > rt) return;

    __shared__ float Qs[64][65], Ks[64][65];
    int tid = threadIdx.x;
    const size_t qbase = ((size_t)(b * TT) + rt * 64) * (3 * EE) + (size_t)h * HD;
    const size_t kbase = ((size_t)(b * TT) + ct * 64) * (3 * EE) + EE + (size_t)h * HD;
    #pragma unroll
    for (int i = 0; i < 16; i++) {
        int lin = i * 256 + tid;
        int r = lin >> 6, c = lin & 63;
        Qs[r][c] = qkv[qbase + (size_t)r * (3 * EE) + c];
        Ks[r][c] = qkv[kbase + (size_t)r * (3 * EE) + c];
    }
    __syncthreads();

    int ty = tid >> 4, tx = tid & 15;
    float acc[4][4] = {};
    #pragma unroll 8
    for (int k = 0; k < 64; k++) {
        float a[4], bv[4];
        #pragma unroll
        for (int i = 0; i < 4; i++) a[i]  = Qs[ty * 4 + i][k];
        #pragma unroll
        for (int j = 0; j < 4; j++) bv[j] = Ks[tx * 4 + j][k];
        #pragma unroll
        for (int i = 0; i < 4; i++)
            #pragma unroll
            for (int j = 0; j < 4; j++)
                acc[i][j] += a[i] * bv[j];
    }

    const float scale = 0.125f;
    size_t abase = (size_t)bh * TT * TT;
    #pragma unroll
    for (int i = 0; i < 4; i++) {
        int t = rt * 64 + ty * 4 + i;
        #pragma unroll
        for (int j = 0; j < 4; j++) {
            int s = ct * 64 + tx * 4 + j;
            if (s <= t) att[abase + (size_t)t * TT + s] = acc[i][j] * scale;
        }
    }
}

// ---------------- causal softmax per row ----------
__global__ void softmax_kernel(float* __restrict__ att)
{
    int r = blockIdx.x;
    int t = r & (TT - 1);
    float* row = att + (size_t)r * TT;
    int len = t + 1;
    int zend = ((t >> 6) + 1) << 6;   // pv only reads up to end of diagonal tile
    int tid = threadIdx.x;
    __shared__ float red[256];

    float m = -INFINITY;
    for (int s = tid; s < len; s += 256) m = fmaxf(m, row[s]);
    red[tid] = m; __syncthreads();
    for (int o = 128; o > 0; o >>= 1) { if (tid < o) red[tid] = fmaxf(red[tid], red[tid + o]); __syncthreads(); }
    m = red[0];
    __syncthreads();

    float sum = 0.f;
    for (int s = tid; s < len; s += 256) { float e = __expf(row[s] - m); row[s] = e; sum += e; }
    red[tid] = sum; __syncthreads();
    for (int o = 128; o > 0; o >>= 1) { if (tid < o) red[tid] += red[tid + o]; __syncthreads(); }
    float inv = 1.0f / red[0];

    for (int s = tid; s < len; s += 256) row[s] *= inv;
    for (int s = len + tid; s < zend; s += 256) row[s] = 0.0f;
}

// ---------------- P @ V with causal s-tile bound ----------------
__global__ void pv_kernel(const float* __restrict__ att,
                          const float* __restrict__ qkv,
                          float* __restrict__ o)
{
    int bh = blockIdx.z;
    int b = bh >> 4, h = bh & 15;
    int rt = blockIdx.y;

    __shared__ float Ps[64][65], Vs[64][65];
    int tid = threadIdx.x;
    int ty = tid >> 4, tx = tid & 15;
    float acc[4][4] = {};

    size_t abase = (size_t)bh * TT * TT + (size_t)rt * 64 * TT;
    size_t vbase = (size_t)b * TT * (3 * EE) + 2 * EE + (size_t)h * HD;

    for (int st = 0; st <= rt; st++) {
        #pragma unroll
        for (int i = 0; i < 16; i++) {
            int lin = i * 256 + tid;
            int rr = lin >> 6, cc = lin & 63;
            Ps[rr][cc] = att[abase + (size_t)rr * TT + st * 64 + cc];
            Vs[rr][cc] = qkv[vbase + (size_t)(st * 64 + rr) * (3 * EE) + cc];
        }
        __syncthreads();
        #pragma unroll 8
        for (int k = 0; k < 64; k++) {
            float a[4], bv[4];
            #pragma unroll
            for (int i = 0; i < 4; i++) a[i]  = Ps[ty * 4 + i][k];
            #pragma unroll
            for (int j = 0; j < 4; j++) bv[j] = Vs[k][tx * 4 + j];
            #pragma unroll
            for (int i = 0; i < 4; i++)
                #pragma unroll
                for (int j = 0; j < 4; j++)
                    acc[i][j] += a[i] * bv[j];
        }
        __syncthreads();
    }

    size_t obase = ((size_t)(b * TT) + rt * 64) * EE + (size_t)h * HD;
    #pragma unroll
    for (int i = 0; i < 4; i++)
        #pragma unroll
        for (int j = 0; j < 4; j++)
            o[obase + (size_t)(ty * 4 + i) * EE + tx * 4 + j] = acc[i][j];
}

// ---------------- launcher ----------------
extern "C" void kernel_launch(void* const* d_in, const int* in_sizes, int n_in,
                              void* d_out, int out_size)
{
    const float* x      = (const float*)d_in[0];
    const float* wq     = (const float*)d_in[1];
    const float* wk     = (const float*)d_in[2];
    const float* wv     = (const float*)d_in[3];
    const float* w_proj = (const float*)d_in[4];
    const float* b_proj = (const float*)d_in[5];
    const float* gamma1 = (const float*)d_in[6];
    const float* beta1  = (const float*)d_in[7];
    const float* gamma2 = (const float*)d_in[8];
    const float* beta2  = (const float*)d_in[9];
    const float* w1     = (const float*)d_in[10];
    const float* b1     = (const float*)d_in[11];
    const float* w2     = (const float*)d_in[12];
    const float* b2     = (const float*)d_in[13];
    float* out = (float*)d_out;

    float *p_h, *p_wqkv, *p_qkv, *p_att, *p_o, *p_x2, *p_h2, *p_ffn;
    cudaGetSymbolAddress((void**)&p_h,    g_h);
    cudaGetSymbolAddress((void**)&p_wqkv, g_wqkv);
    cudaGetSymbolAddress((void**)&p_qkv,  g_qkv);
    cudaGetSymbolAddress((void**)&p_att,  g_att);
    cudaGetSymbolAddress((void**)&p_o,    g_o);
    cudaGetSymbolAddress((void**)&p_x2,   g_x2);
    cudaGetSymbolAddress((void**)&p_h2,   g_h2);
    cudaGetSymbolAddress((void**)&p_ffn,  g_ffn);

    // 1) LN1
    ln_kernel<<<NTOK, 256>>>(x, gamma1, beta1, p_h);
    // 2) pack per-head weights into [E,3E]
    pack_w_kernel<<<(3 * EE * EE) / 256, 256>>>(wq, wk, wv, p_wqkv);
    // 3) QKV = h @ Wqkv
    mm_tf32<0><<<dim3(3 * EE / 128, NTOK / 128), 256>>>(p_h, p_wqkv, nullptr, nullptr, p_qkv, NTOK, 3 * EE, EE);
    // 4) scores (causal tiles only)
    qk_kernel<<<dim3(TT / 64, TT / 64, BHN), 256>>>(p_qkv, p_att);
    // 5) softmax per row
    softmax_kernel<<<BHN * TT, 256>>>(p_att);
    // 6) O = P @ V
    pv_kernel<<<dim3(1, TT / 64, BHN), 256>>>(p_att, p_qkv, p_o);
    // 7) x2 = h + O @ w_proj + b_proj
    mm_tf32<3><<<dim3(EE / 128, NTOK / 128), 256>>>(p_o, w_proj, b_proj, p_h, p_x2, NTOK, EE, EE);
    // 8) LN2
    ln_kernel<<<NTOK, 256>>>(p_x2, gamma2, beta2, p_h2);
    // 9) ffn = relu(h2 @ w1 + b1)
    mm_tf32<2><<<dim3(DFF / 128, NTOK / 128), 256>>>(p_h2, w1, b1, nullptr, p_ffn, NTOK, DFF, EE);
    // 10) out = h2 + ffn @ w2 + b2
    mm_tf32<3><<<dim3(EE / 128, NTOK / 128), 256>>>(p_ffn, w2, b2, p_h2, out, NTOK, EE, DFF);
}

// round 3
// speedup vs baseline: 3.9302x; 1.7905x over previous
#include <cuda_runtime.h>
#include <math.h>
#include <stdint.h>

// Problem constants
#define BB 2
#define TT 2048
#define EE 1024
#define HH 16
#define HD 64
#define DFF 4096
#define NTOK (BB*TT)          // 4096
#define BHN (BB*HH)           // 32

// ---------------- scratch (device globals; no allocation allowed) ----------------
__device__ float g_h   [NTOK*EE];          // LN1 output
__device__ float g_wqkv[EE*3*EE];          // packed [E, 3E] weights
__device__ float g_qkv [NTOK*3*EE];        // q|k|v per token
__device__ float g_o   [NTOK*EE];          // attention out (heads concat)
__device__ float g_x2  [NTOK*EE];          // h + proj
__device__ float g_h2  [NTOK*EE];          // LN2 output
__device__ float g_ffn [NTOK*DFF];         // relu(h2@w1+b1)

// ---------------- helpers ----------------
__device__ __forceinline__ uint32_t cvt_tf32(float x) {
    uint32_t r;
    asm("cvt.rna.tf32.f32 %0, %1;" : "=r"(r) : "f"(x));
    return r;
}
__device__ __forceinline__ float cvt_tf32f(float x) {
    return __uint_as_float(cvt_tf32(x));
}
__device__ __forceinline__ void cp16(void* s, const void* g) {
    uint32_t sa = (uint32_t)__cvta_generic_to_shared(s);
    asm volatile("cp.async.cg.shared.global [%0], [%1], 16;" :: "r"(sa), "l"(g));
}
__device__ __forceinline__ void cp_commit() { asm volatile("cp.async.commit_group;"); }
template<int N> __device__ __forceinline__ void cp_wait() {
    asm volatile("cp.async.wait_group %0;" :: "n"(N));
}
__device__ __forceinline__ void mma_tf32(float acc[4], const uint32_t a[4],
                                         uint32_t b0, uint32_t b1) {
    asm volatile(
        "mma.sync.aligned.m16n8k8.row.col.f32.tf32.tf32.f32 "
        "{%0,%1,%2,%3},{%4,%5,%6,%7},{%8,%9},{%0,%1,%2,%3};"
        : "+f"(acc[0]), "+f"(acc[1]), "+f"(acc[2]), "+f"(acc[3])
        : "r"(a[0]), "r"(a[1]), "r"(a[2]), "r"(a[3]), "r"(b0), "r"(b1));
}

// ---------------- LayerNorm ----------------
__global__ void ln_kernel(const float* __restrict__ x,
                          const float* __restrict__ gamma,
                          const float* __restrict__ beta,
                          float* __restrict__ y)
{
    int row = blockIdx.x;
    const float* xr = x + (size_t)row * EE;
    float* yr = y + (size_t)row * EE;
    int tid = threadIdx.x;
    __shared__ float red[256];

    float s = 0.f;
    for (int i = tid; i < EE; i += 256) s += xr[i];
    red[tid] = s; __syncthreads();
    for (int o = 128; o > 0; o >>= 1) { if (tid < o) red[tid] += red[tid + o]; __syncthreads(); }
    float mean = red[0] * (1.0f / EE);
    __syncthreads();

    float v = 0.f;
    for (int i = tid; i < EE; i += 256) { float d = xr[i] - mean; v += d * d; }
    red[tid] = v; __syncthreads();
    for (int o = 128; o > 0; o >>= 1) { if (tid < o) red[tid] += red[tid + o]; __syncthreads(); }
    float inv = rsqrtf(red[0] * (1.0f / EE) + 1e-5f);

    for (int i = tid; i < EE; i += 256)
        yr[i] = (xr[i] - mean) * inv * gamma[i] + beta[i];
}

// ---------------- pack wq/wk/wv [H,E,hd] -> [E, 3E] ----------------
__global__ void pack_w_kernel(const float* __restrict__ wq,
                              const float* __restrict__ wk,
                              const float* __restrict__ wv,
                              float* __restrict__ out)
{
    int idx = blockIdx.x * blockDim.x + threadIdx.x;
    const int total = 3 * EE * EE;
    if (idx >= total) return;
    int part = idx / (EE * EE);
    int rem  = idx % (EE * EE);
    int e = rem / EE;
    int c = rem % EE;
    const float* w = (part == 0) ? wq : (part == 1) ? wk : wv;
    out[(size_t)e * (3 * EE) + part * EE + c] =
        w[(size_t)(c >> 6) * (EE * HD) + (size_t)e * HD + (c & 63)];
}

// ---------------- tf32 tensor-core GEMM (same as R1) -----------
template <int EPI>
__global__ void __launch_bounds__(256, 2)
mm_tf32(const float* __restrict__ A,
        const float* __restrict__ B,
        const float* __restrict__ bias,
        const float* __restrict__ res,
        float* __restrict__ C,
        int M, int N, int K)
{
    const int BM = 128, BN = 128, BK = 16;
    __shared__ float As[2][BM][BK + 4];
    __shared__ float Bs[2][BK][BN + 8];

    int tid = threadIdx.x;
    int lane = tid & 31, wid = tid >> 5;
    int wm = wid >> 1, wn = wid & 1;
    int g = lane >> 2, c = lane & 3;
    int rowBase = blockIdx.y * BM;
    int colBase = blockIdx.x * BN;

    float acc[2][8][4];
    #pragma unroll
    for (int i = 0; i < 2; i++)
        #pragma unroll
        for (int j = 0; j < 8; j++)
            #pragma unroll
            for (int k = 0; k < 4; k++) acc[i][j][k] = 0.f;

    auto load_stage = [&](int buf, int kk) {
        #pragma unroll
        for (int i = 0; i < 2; i++) {
            int idx = i * 256 + tid;
            int m = idx >> 2, ch = idx & 3;
            cp16(&As[buf][m][ch * 4], A + (size_t)(rowBase + m) * K + kk + ch * 4);
        }
        #pragma unroll
        for (int i = 0; i < 2; i++) {
            int idx = i * 256 + tid;
            int r = idx >> 5, ch = idx & 31;
            cp16(&Bs[buf][r][ch * 4], B + (size_t)(kk + r) * N + colBase + ch * 4);
        }
        cp_commit();
    };

    load_stage(0, 0);
    int nk = K / BK;
    for (int k0 = 0; k0 < nk; k0++) {
        int cur = k0 & 1;
        if (k0 + 1 < nk) { load_stage(cur ^ 1, (k0 + 1) * BK); cp_wait<1>(); }
        else            { cp_wait<0>(); }
        __syncthreads();

        #pragma unroll
        for (int ks = 0; ks < 2; ks++) {
            int kb = ks * 8;
            uint32_t af[2][4];
            #pragma unroll
            for (int mt = 0; mt < 2; mt++) {
                int m0 = wm * 32 + mt * 16;
                af[mt][0] = cvt_tf32(As[cur][m0 + g    ][kb + c    ]);
                af[mt][1] = cvt_tf32(As[cur][m0 + g + 8][kb + c    ]);
                af[mt][2] = cvt_tf32(As[cur][m0 + g    ][kb + c + 4]);
                af[mt][3] = cvt_tf32(As[cur][m0 + g + 8][kb + c + 4]);
            }
            uint32_t bf[8][2];
            #pragma unroll
            for (int nt = 0; nt < 8; nt++) {
                int n0 = wn * 64 + nt * 8;
                bf[nt][0] = cvt_tf32(Bs[cur][kb + c    ][n0 + g]);
                bf[nt][1] = cvt_tf32(Bs[cur][kb + c + 4][n0 + g]);
            }
            #pragma unroll
            for (int mt = 0; mt < 2; mt++)
                #pragma unroll
                for (int nt = 0; nt < 8; nt++)
                    mma_tf32(acc[mt][nt], af[mt], bf[nt][0], bf[nt][1]);
        }
        __syncthreads();
    }

    #pragma unroll
    for (int mt = 0; mt < 2; mt++) {
        int row0 = rowBase + wm * 32 + mt * 16 + g;
        #pragma unroll
        for (int nt = 0; nt < 8; nt++) {
            int col = colBase + wn * 64 + nt * 8 + c * 2;
            float v0 = acc[mt][nt][0], v1 = acc[mt][nt][1];
            float v2 = acc[mt][nt][2], v3 = acc[mt][nt][3];
            if (EPI >= 1) {
                float b0 = bias[col], b1 = bias[col + 1];
                v0 += b0; v1 += b1; v2 += b0; v3 += b1;
            }
            if (EPI == 2) {
                v0 = fmaxf(v0, 0.f); v1 = fmaxf(v1, 0.f);
                v2 = fmaxf(v2, 0.f); v3 = fmaxf(v3, 0.f);
            }
            if (EPI == 3) {
                v0 += res[(size_t)row0 * N + col];
                v1 += res[(size_t)row0 * N + col + 1];
                v2 += res[(size_t)(row0 + 8) * N + col];
                v3 += res[(size_t)(row0 + 8) * N + col + 1];
            }
            *reinterpret_cast<float2*>(&C[(size_t)row0 * N + col])       = make_float2(v0, v1);
            *reinterpret_cast<float2*>(&C[(size_t)(row0 + 8) * N + col]) = make_float2(v2, v3);
        }
    }
}

// ---------------- fused flash attention ----------------
// grid: (T/64, BHN); block: 128 (4 warps, 16 query rows each)
// Br = Bc = 64, hd = 64. tf32 MMA for S and PV, online softmax.
__global__ void __launch_bounds__(128)
flash_kernel(const float* __restrict__ qkv, float* __restrict__ o)
{
    __shared__ float KP[64][68];   // K tile, then reused as P tile
    __shared__ float Vs[64][72];

    int bh = blockIdx.y;
    int b = bh >> 4, h = bh & 15;
    int rt = gridDim.x - 1 - blockIdx.x;   // heavy CTAs first
    int q0 = rt * 64;

    int tid = threadIdx.x;
    int lane = tid & 31, wid = tid >> 5;
    int g = lane >> 2, c = lane & 3;
    int wbase = wid * 16;

    // Q fragments, pre-scaled by 1/sqrt(hd), tf32
    uint32_t qf[8][4];
    const float* Qb = qkv + ((size_t)(b * TT + q0 + wbase)) * (3 * EE) + (size_t)h * HD;
    #pragma unroll
    for (int k8 = 0; k8 < 8; k8++) {
        int kb = k8 * 8;
        qf[k8][0] = cvt_tf32(0.125f * Qb[(size_t)g       * (3 * EE) + kb + c]);
        qf[k8][1] = cvt_tf32(0.125f * Qb[(size_t)(g + 8) * (3 * EE) + kb + c]);
        qf[k8][2] = cvt_tf32(0.125f * Qb[(size_t)g       * (3 * EE) + kb + c + 4]);
        qf[k8][3] = cvt_tf32(0.125f * Qb[(size_t)(g + 8) * (3 * EE) + kb + c + 4]);
    }

    float m0 = -INFINITY, m1 = -INFINITY, l0 = 0.f, l1 = 0.f;
    float oacc[8][4];
    #pragma unroll
    for (int nt = 0; nt < 8; nt++)
        #pragma unroll
        for (int k = 0; k < 4; k++) oacc[nt][k] = 0.f;

    for (int st = 0; st <= rt; st++) {
        __syncthreads();  // previous tile fully consumed (K overwrite, V reload)

        // load K,V tiles [64 x 64], convert to tf32 at store
        const float* Kg = qkv + ((size_t)(b * TT + st * 64)) * (3 * EE) + EE + (size_t)h * HD;
        const float* Vg = Kg + EE;
        #pragma unroll
        for (int i = 0; i < 8; i++) {
            int idx = i * 128 + tid;
            int r = idx >> 4, ch = (idx & 15) * 4;
            float4 kv = *(const float4*)(Kg + (size_t)r * (3 * EE) + ch);
            KP[r][ch]     = cvt_tf32f(kv.x);
            KP[r][ch + 1] = cvt_tf32f(kv.y);
            KP[r][ch + 2] = cvt_tf32f(kv.z);
            KP[r][ch + 3] = cvt_tf32f(kv.w);
            float4 vv = *(const float4*)(Vg + (size_t)r * (3 * EE) + ch);
            Vs[r][ch]     = cvt_tf32f(vv.x);
            Vs[r][ch + 1] = cvt_tf32f(vv.y);
            Vs[r][ch + 2] = cvt_tf32f(vv.z);
            Vs[r][ch + 3] = cvt_tf32f(vv.w);
        }
        __syncthreads();

        // S = Q @ K^T : per warp 16 x 64
        float sacc[8][4];
        #pragma unroll
        for (int nt = 0; nt < 8; nt++)
            #pragma unroll
            for (int k = 0; k < 4; k++) sacc[nt][k] = 0.f;

        #pragma unroll
        for (int k8 = 0; k8 < 8; k8++) {
            int kb = k8 * 8;
            #pragma unroll
            for (int nt = 0; nt < 8; nt++) {
                uint32_t b0 = __float_as_uint(KP[nt * 8 + g][kb + c]);
                uint32_t b1 = __float_as_uint(KP[nt * 8 + g][kb + c + 4]);
                mma_tf32(sacc[nt], qf[k8], b0, b1);
            }
        }

        // causal mask on diagonal tile only
        if (st == rt) {
            int ql0 = wbase + g, ql1 = ql0 + 8;
            #pragma unroll
            for (int nt = 0; nt < 8; nt++) {
                int kl = nt * 8 + 2 * c;
                if (kl     > ql0) sacc[nt][0] = -1e30f;
                if (kl + 1 > ql0) sacc[nt][1] = -1e30f;
                if (kl     > ql1) sacc[nt][2] = -1e30f;
                if (kl + 1 > ql1) sacc[nt][3] = -1e30f;
            }
        }

        // online softmax: rows g (acc 0,1) and g+8 (acc 2,3)
        float mx0 = -1e30f, mx1 = -1e30f;
        #pragma unroll
        for (int nt = 0; nt < 8; nt++) {
            mx0 = fmaxf(mx0, fmaxf(sacc[nt][0], sacc[nt][1]));
            mx1 = fmaxf(mx1, fmaxf(sacc[nt][2], sacc[nt][3]));
        }
        mx0 = fmaxf(mx0, __shfl_xor_sync(0xffffffffu, mx0, 1));
        mx0 = fmaxf(mx0, __shfl_xor_sync(0xffffffffu, mx0, 2));
        mx1 = fmaxf(mx1, __shfl_xor_sync(0xffffffffu, mx1, 1));
        mx1 = fmaxf(mx1, __shfl_xor_sync(0xffffffffu, mx1, 2));

        float mn0 = fmaxf(m0, mx0), mn1 = fmaxf(m1, mx1);
        float al0 = __expf(m0 - mn0), al1 = __expf(m1 - mn1);
        m0 = mn0; m1 = mn1;

        float rs0 = 0.f, rs1 = 0.f;
        #pragma unroll
        for (int nt = 0; nt < 8; nt++) {
            float p0 = __expf(sacc[nt][0] - m0);
            float p1 = __expf(sacc[nt][1] - m0);
            float p2 = __expf(sacc[nt][2] - m1);
            float p3 = __expf(sacc[nt][3] - m1);
            sacc[nt][0] = p0; sacc[nt][1] = p1; sacc[nt][2] = p2; sacc[nt][3] = p3;
            rs0 += p0 + p1; rs1 += p2 + p3;
        }
        rs0 += __shfl_xor_sync(0xffffffffu, rs0, 1);
        rs0 += __shfl_xor_sync(0xffffffffu, rs0, 2);
        rs1 += __shfl_xor_sync(0xffffffffu, rs1, 1);
        rs1 += __shfl_xor_sync(0xffffffffu, rs1, 2);
        l0 = l0 * al0 + rs0;
        l1 = l1 * al1 + rs1;

        #pragma unroll
        for (int nt = 0; nt < 8; nt++) {
            oacc[nt][0] *= al0; oacc[nt][1] *= al0;
            oacc[nt][2] *= al1; oacc[nt][3] *= al1;
        }

        // store P into KP (K no longer needed by anyone)
        __syncthreads();
        #pragma unroll
        for (int nt = 0; nt < 8; nt++) {
            int col = nt * 8 + 2 * c;
            KP[wbase + g    ][col]     = cvt_tf32f(sacc[nt][0]);
            KP[wbase + g    ][col + 1] = cvt_tf32f(sacc[nt][1]);
            KP[wbase + g + 8][col]     = cvt_tf32f(sacc[nt][2]);
            KP[wbase + g + 8][col + 1] = cvt_tf32f(sacc[nt][3]);
        }
        __syncwarp();  // each warp reads only its own 16 P rows

        // O += P @ V : contraction over 64 keys
        #pragma unroll
        for (int k8 = 0; k8 < 8; k8++) {
            int kb = k8 * 8;
            uint32_t af[4];
            af[0] = __float_as_uint(KP[wbase + g    ][kb + c]);
            af[1] = __float_as_uint(KP[wbase + g + 8][kb + c]);
            af[2] = __float_as_uint(KP[wbase + g    ][kb + c + 4]);
            af[3] = __float_as_uint(KP[wbase + g + 8][kb + c + 4]);
            #pragma unroll
            for (int nt = 0; nt < 8; nt++) {
                uint32_t b0 = __float_as_uint(Vs[kb + c    ][nt * 8 + g]);
                uint32_t b1 = __float_as_uint(Vs[kb + c + 4][nt * 8 + g]);
                mma_tf32(oacc[nt], af, b0, b1);
            }
        }
    }

    // epilogue: normalize and write O
    float i0 = 1.0f / l0, i1 = 1.0f / l1;
    float* Ob = o + ((size_t)(b * TT + q0 + wbase)) * EE + (size_t)h * HD;
    #pragma unroll
    for (int nt = 0; nt < 8; nt++) {
        int col = nt * 8 + 2 * c;
        *(float2*)&Ob[(size_t)g * EE + col] =
            make_float2(oacc[nt][0] * i0, oacc[nt][1] * i0);
        *(float2*)&Ob[(size_t)(g + 8) * EE + col] =
            make_float2(oacc[nt][2] * i1, oacc[nt][3] * i1);
    }
}

// ---------------- launcher ----------------
extern "C" void kernel_launch(void* const* d_in, const int* in_sizes, int n_in,
                              void* d_out, int out_size)
{
    const float* x      = (const float*)d_in[0];
    const float* wq     = (const float*)d_in[1];
    const float* wk     = (const float*)d_in[2];
    const float* wv     = (const float*)d_in[3];
    const float* w_proj = (const float*)d_in[4];
    const float* b_proj = (const float*)d_in[5];
    const float* gamma1 = (const float*)d_in[6];
    const float* beta1  = (const float*)d_in[7];
    const float* gamma2 = (const float*)d_in[8];
    const float* beta2  = (const float*)d_in[9];
    const float* w1     = (const float*)d_in[10];
    const float* b1     = (const float*)d_in[11];
    const float* w2     = (const float*)d_in[12];
    const float* b2     = (const float*)d_in[13];
    float* out = (float*)d_out;

    float *p_h, *p_wqkv, *p_qkv, *p_o, *p_x2, *p_h2, *p_ffn;
    cudaGetSymbolAddress((void**)&p_h,    g_h);
    cudaGetSymbolAddress((void**)&p_wqkv, g_wqkv);
    cudaGetSymbolAddress((void**)&p_qkv,  g_qkv);
    cudaGetSymbolAddress((void**)&p_o,    g_o);
    cudaGetSymbolAddress((void**)&p_x2,   g_x2);
    cudaGetSymbolAddress((void**)&p_h2,   g_h2);
    cudaGetSymbolAddress((void**)&p_ffn,  g_ffn);

    // 1) LN1
    ln_kernel<<<NTOK, 256>>>(x, gamma1, beta1, p_h);
    // 2) pack per-head weights into [E,3E]
    pack_w_kernel<<<(3 * EE * EE) / 256, 256>>>(wq, wk, wv, p_wqkv);
    // 3) QKV = h @ Wqkv
    mm_tf32<0><<<dim3(3 * EE / 128, NTOK / 128), 256>>>(p_h, p_wqkv, nullptr, nullptr, p_qkv, NTOK, 3 * EE, EE);
    // 4-6) fused flash attention
    flash_kernel<<<dim3(TT / 64, BHN), 128>>>(p_qkv, p_o);
    // 7) x2 = h + O @ w_proj + b_proj
    mm_tf32<3><<<dim3(EE / 128, NTOK / 128), 256>>>(p_o, w_proj, b_proj, p_h, p_x2, NTOK, EE, EE);
    // 8) LN2
    ln_kernel<<<NTOK, 256>>>(p_x2, gamma2, beta2, p_h2);
    // 9) ffn = relu(h2 @ w1 + b1)
    mm_tf32<2><<<dim3(DFF / 128, NTOK / 128), 256>>>(p_h2, w1, b1, nullptr, p_ffn, NTOK, DFF, EE);
    // 10) out = h2 + ffn @ w2 + b2
    mm_tf32<3><<<dim3(EE / 128, NTOK / 128), 256>>>(p_ffn, w2, b2, p_h2, out, NTOK, EE, DFF);
}